// round 9
// baseline (speedup 1.0000x reference)
#include <cuda_runtime.h>
#include <cstdint>
#include <math.h>

#define Tn   1568
#define Dm   768
#define FFd  3072
#define NEx  8
#define HDh  64
#define KSP2 3          // split-K factor for FF2 (288 eff. CTAs ~= one full wave)
#define STG  3          // cp.async pipeline stages
#define BKs  32         // K-depth per stage

// ---- scratch (allocation-free: __device__ globals) ----
__device__ float g_x1[Tn * Dm];            // residual after attention
__device__ float g_h2[Tn * Dm];            // LN2 output, tf32-rounded (MoE GEMM A)
__device__ float g_hbuf[Tn * FFd];         // FF1 activations, tf32-rounded, compact
__device__ float g_part[KSP2 * Tn * Dm];   // FF2 split-K partials
__device__ int   g_top1[Tn];
__device__ int   g_perm[Tn];
__device__ int   g_off[NEx + 1];

__device__ __forceinline__ unsigned f2tf32(float f) {
    unsigned r;
    asm("cvt.rna.tf32.f32 %0, %1;" : "=r"(r) : "f"(f));
    return r;
}

// ============================================================
// Kernel 1: LN1 + v-projection + residual + LN2 + gating
// Attention collapses algebraically: out_head(h) = v for all h.
// ============================================================
__global__ __launch_bounds__(256) void prep_kernel(
    const float* __restrict__ x,
    const float* __restrict__ ln1g, const float* __restrict__ ln1b,
    const float* __restrict__ Wv,   const float* __restrict__ bv,
    const float* __restrict__ ln2g, const float* __restrict__ ln2b,
    const float* __restrict__ Wg,   const float* __restrict__ bg)
{
    __shared__ float xs[4][Dm];
    __shared__ float hs[4][Dm];
    __shared__ float vs[4][HDh];
    __shared__ float red[16];

    const int tid  = threadIdx.x;
    const int base = blockIdx.x * 4;

    for (int t = 0; t < 4; t++) {
        const float* xr = x + (size_t)(base + t) * Dm;
        float s = 0.f, ss = 0.f, lv[3];
        #pragma unroll
        for (int i = 0; i < 3; i++) {
            int c = tid + i * 256;
            float v = xr[c];
            lv[i] = v; xs[t][c] = v; s += v; ss += v * v;
        }
        #pragma unroll
        for (int o = 16; o; o >>= 1) {
            s  += __shfl_xor_sync(0xffffffffu, s,  o);
            ss += __shfl_xor_sync(0xffffffffu, ss, o);
        }
        if ((tid & 31) == 0) { red[tid >> 5] = s; red[8 + (tid >> 5)] = ss; }
        __syncthreads();
        s = 0.f; ss = 0.f;
        #pragma unroll
        for (int i = 0; i < 8; i++) { s += red[i]; ss += red[8 + i]; }
        float mu   = s * (1.f / Dm);
        float var  = ss * (1.f / Dm) - mu * mu;
        float rstd = rsqrtf(var + 1e-5f);
        #pragma unroll
        for (int i = 0; i < 3; i++) {
            int c = tid + i * 256;
            hs[t][c] = (lv[i] - mu) * rstd * ln1g[c] + ln1b[c];
        }
        __syncthreads();
    }

    {   // v = LN1(x) @ Wv + bv
        const int t2 = tid >> 6, j = tid & 63;
        float a0 = 0.f, a1 = 0.f, a2 = 0.f, a3 = 0.f;
        for (int k = 0; k < Dm; k += 4) {
            a0 += hs[t2][k + 0] * Wv[(k + 0) * HDh + j];
            a1 += hs[t2][k + 1] * Wv[(k + 1) * HDh + j];
            a2 += hs[t2][k + 2] * Wv[(k + 2) * HDh + j];
            a3 += hs[t2][k + 3] * Wv[(k + 3) * HDh + j];
        }
        vs[t2][j] = (a0 + a1) + (a2 + a3) + bv[j];
    }
    __syncthreads();

    for (int t = 0; t < 4; t++) {   // residual + LN2
        const int tok = base + t;
        float s = 0.f, ss = 0.f, lv[3];
        #pragma unroll
        for (int i = 0; i < 3; i++) {
            int c = tid + i * 256;
            float v = xs[t][c] + vs[t][c & (HDh - 1)];
            lv[i] = v; s += v; ss += v * v;
            g_x1[(size_t)tok * Dm + c] = v;
        }
        #pragma unroll
        for (int o = 16; o; o >>= 1) {
            s  += __shfl_xor_sync(0xffffffffu, s,  o);
            ss += __shfl_xor_sync(0xffffffffu, ss, o);
        }
        if ((tid & 31) == 0) { red[tid >> 5] = s; red[8 + (tid >> 5)] = ss; }
        __syncthreads();
        s = 0.f; ss = 0.f;
        #pragma unroll
        for (int i = 0; i < 8; i++) { s += red[i]; ss += red[8 + i]; }
        float mu   = s * (1.f / Dm);
        float var  = ss * (1.f / Dm) - mu * mu;
        float rstd = rsqrtf(var + 1e-5f);
        #pragma unroll
        for (int i = 0; i < 3; i++) {
            int c = tid + i * 256;
            float h = (lv[i] - mu) * rstd * ln2g[c] + ln2b[c];
            hs[t][c] = h;                                  // fp32 for gating
            g_h2[(size_t)tok * Dm + c] = __uint_as_float(f2tf32(h));  // tf32-rna for GEMM A
        }
        __syncthreads();
    }

    // gate logits + argmax (fp32)
    const int wid = tid >> 5, lane = tid & 31;
    if (wid < 4) {
        float lg[8];
        #pragma unroll
        for (int e = 0; e < 8; e++) lg[e] = 0.f;
        for (int k = lane; k < Dm; k += 32) {
            float h = hs[wid][k];
            #pragma unroll
            for (int e = 0; e < 8; e++) lg[e] += h * Wg[k * 8 + e];
        }
        #pragma unroll
        for (int e = 0; e < 8; e++)
            #pragma unroll
            for (int o = 16; o; o >>= 1) lg[e] += __shfl_xor_sync(0xffffffffu, lg[e], o);
        if (lane == 0) {
            float best = lg[0] + bg[0]; int bi = 0;
            #pragma unroll
            for (int e = 1; e < 8; e++) {
                float v = lg[e] + bg[e];
                if (v > best) { best = v; bi = e; }
            }
            g_top1[base + wid] = bi;
        }
    }
}

// ============================================================
// Kernel 2: bucket tokens by expert (single block)
// ============================================================
__global__ void bucket_kernel()
{
    __shared__ int cnt[NEx];
    __shared__ int cur[NEx];
    const int tid = threadIdx.x;
    if (tid < NEx) cnt[tid] = 0;
    __syncthreads();
    for (int i = tid; i < Tn; i += 256) atomicAdd(&cnt[g_top1[i]], 1);
    __syncthreads();
    if (tid == 0) {
        int acc = 0;
        for (int e = 0; e < NEx; e++) { g_off[e] = acc; cur[e] = acc; acc += cnt[e]; }
        g_off[NEx] = acc;
    }
    __syncthreads();
    for (int i = tid; i < Tn; i += 256) {
        int e = g_top1[i];
        int p = atomicAdd(&cur[e], 1);
        g_perm[p] = i;
    }
}

__device__ __forceinline__ float gelu_exact(float v) { return v * normcdff(v); }

__device__ __forceinline__ void mma_tf32(float* c,
    unsigned a0, unsigned a1, unsigned a2, unsigned a3,
    unsigned b0, unsigned b1)
{
    asm volatile(
        "mma.sync.aligned.m16n8k8.row.col.f32.tf32.tf32.f32 "
        "{%0,%1,%2,%3}, {%4,%5,%6,%7}, {%8,%9}, {%0,%1,%2,%3};"
        : "+f"(c[0]), "+f"(c[1]), "+f"(c[2]), "+f"(c[3])
        : "r"(a0), "r"(a1), "r"(a2), "r"(a3), "r"(b0), "r"(b1));
}

__device__ __forceinline__ uint32_t smem_u32(const void* p) {
    return (uint32_t)__cvta_generic_to_shared(p);
}
__device__ __forceinline__ void cp16(uint32_t dst, const void* src) {
    asm volatile("cp.async.cg.shared.global [%0], [%1], 16;" :: "r"(dst), "l"(src));
}
__device__ __forceinline__ void cp16z(uint32_t dst, const void* src, int sz) {
    asm volatile("cp.async.cg.shared.global [%0], [%1], 16, %2;" :: "r"(dst), "l"(src), "r"(sz));
}

// ============================================================
// TF32 tensor-core MoE GEMM, cp.async 3-stage pipeline, BK=32 per
// stage (one barrier per 64 HMMA/warp), static stage indices.
// Block tile 128x128, 8 warps of 32x64.
// A smem [128][36] (m-major; bank 4m+k -> conflict-free frag loads)
// B smem [32][136] (k-major; bank 8k+n -> conflict-free frag loads)
// Weights fed as raw f32 (HW tf32 truncation); activations pre-rounded rna.
// ============================================================
#define LDAA 36
#define LDBB 136
#define GEMM_SMEM_BYTES ((STG * 128 * LDAA + STG * BKs * LDBB) * 4)

template<int K, int N, bool IS_FF1, int KSPLIT>
__global__ __launch_bounds__(256, 2) void moe_gemm_cp(
    const float* __restrict__ W, const float* __restrict__ bias)
{
    const int e  = blockIdx.z / KSPLIT;
    const int kc = blockIdx.z % KSPLIT;
    constexpr int KS = K / KSPLIT;
    constexpr int NITER = KS / BKs;

    const int m0 = g_off[e];
    const int Me = g_off[e + 1] - m0;
    const int mt = blockIdx.y;
    if (mt * 128 >= Me) return;
    const int nt = blockIdx.x;

    extern __shared__ float smem[];
    float (*As)[128][LDAA] = (float (*)[128][LDAA])smem;
    float (*Bs)[BKs][LDBB] = (float (*)[BKs][LDBB])(smem + STG * 128 * LDAA);

    const int tid  = threadIdx.x;
    const int lane = tid & 31;
    const int w    = tid >> 5;
    const int grp  = lane >> 2, tig = lane & 3;
    const int wrow = (w & 3) * 32;
    const int wcol = (w >> 2) * 64;

    // ---- cp.async loader assignments ----
    const int ar  = tid >> 1;            // A row 0..127 (2 threads/row)
    const int ak  = (tid & 1) * 16;      // A k-half (floats)
    const int br0 = tid >> 5;            // B k-rows br0 + {0,8,16,24}
    const int bnq = (tid & 31) * 4;      // B n-offset (floats)

    const int  mloc   = mt * 128 + ar;
    const bool avalid = mloc < Me;
    const int  apos   = m0 + (avalid ? mloc : 0);
    const int  asz    = avalid ? 16 : 0;
    const float* __restrict__ arp =
        (IS_FF1 ? &g_h2[(size_t)g_perm[apos] * K] : &g_hbuf[(size_t)apos * K])
        + kc * KS + ak;
    const float* __restrict__ Bbase =
        W + (size_t)e * K * N + (size_t)(kc * KS) * N + (size_t)nt * 128 + bnq;

    #define LOAD_STAGE(k0, st)                                                        \
        do {                                                                          \
            cp16z(smem_u32(&As[st][ar][ak + 0]),  arp + (k0) + 0,  asz);              \
            cp16z(smem_u32(&As[st][ar][ak + 4]),  arp + (k0) + 4,  asz);              \
            cp16z(smem_u32(&As[st][ar][ak + 8]),  arp + (k0) + 8,  asz);              \
            cp16z(smem_u32(&As[st][ar][ak + 12]), arp + (k0) + 12, asz);              \
            cp16(smem_u32(&Bs[st][br0     ][bnq]), Bbase + (size_t)((k0) + br0     ) * N); \
            cp16(smem_u32(&Bs[st][br0 +  8][bnq]), Bbase + (size_t)((k0) + br0 +  8) * N); \
            cp16(smem_u32(&Bs[st][br0 + 16][bnq]), Bbase + (size_t)((k0) + br0 + 16) * N); \
            cp16(smem_u32(&Bs[st][br0 + 24][bnq]), Bbase + (size_t)((k0) + br0 + 24) * N); \
            asm volatile("cp.async.commit_group;");                                   \
        } while (0)

    float acc[2][8][4];
    #pragma unroll
    for (int i = 0; i < 2; i++)
        #pragma unroll
        for (int j = 0; j < 8; j++)
            #pragma unroll
            for (int r = 0; r < 4; r++) acc[i][j][r] = 0.f;

    // one full BK=32 stage of compute, stage index static
    #define ITER_BODY(st, kit)                                                        \
        do {                                                                          \
            if ((kit) + STG - 1 < NITER) {                                            \
                LOAD_STAGE(((kit) + STG - 1) * BKs, ((st) + STG - 1) % STG);          \
            } else {                                                                  \
                asm volatile("cp.async.commit_group;");                               \
            }                                                                         \
            _Pragma("unroll")                                                         \
            for (int ks = 0; ks < 4; ks++) {                                          \
                const int kk = ks * 8;                                                \
                unsigned af[2][4];                                                    \
                _Pragma("unroll")                                                     \
                for (int mi = 0; mi < 2; mi++) {                                      \
                    const int mb = wrow + mi * 16;                                    \
                    af[mi][0] = __float_as_uint(As[st][mb + grp    ][kk + tig    ]);  \
                    af[mi][1] = __float_as_uint(As[st][mb + grp + 8][kk + tig    ]);  \
                    af[mi][2] = __float_as_uint(As[st][mb + grp    ][kk + tig + 4]);  \
                    af[mi][3] = __float_as_uint(As[st][mb + grp + 8][kk + tig + 4]);  \
                }                                                                     \
                _Pragma("unroll")                                                     \
                for (int nj = 0; nj < 8; nj++) {                                      \
                    const int nb = wcol + nj * 8;                                     \
                    unsigned b0 = __float_as_uint(Bs[st][kk + tig    ][nb + grp]);    \
                    unsigned b1 = __float_as_uint(Bs[st][kk + tig + 4][nb + grp]);    \
                    mma_tf32(acc[0][nj], af[0][0], af[0][1], af[0][2], af[0][3], b0, b1); \
                    mma_tf32(acc[1][nj], af[1][0], af[1][1], af[1][2], af[1][3], b0, b1); \
                }                                                                     \
            }                                                                         \
            asm volatile("cp.async.wait_group 1;");                                   \
            __syncthreads();                                                          \
        } while (0)

    // prologue: stages 0,1 in flight; compute may start once stage 0 lands
    LOAD_STAGE(0, 0);
    LOAD_STAGE(BKs, 1);
    asm volatile("cp.async.wait_group 1;");
    __syncthreads();

    int it = 0;
    for (; it + STG <= NITER; it += STG) {
        ITER_BODY(0, it + 0);
        ITER_BODY(1, it + 1);
        ITER_BODY(2, it + 2);
    }
    // statically-peeled remainder (NITER % STG is constexpr; dead code folds)
    if (NITER % STG > 0) ITER_BODY(0, (NITER / STG) * STG + 0);
    if (NITER % STG > 1) ITER_BODY(1, (NITER / STG) * STG + 1);

    #undef ITER_BODY
    #undef LOAD_STAGE

    // ---- epilogue ----
    // element (mi, nj, reg): row = wrow + mi*16 + grp + 8*(reg>>1)
    //                        col = wcol + nj*8 + 2*tig + (reg&1)
    #pragma unroll
    for (int mi = 0; mi < 2; mi++) {
        #pragma unroll
        for (int half = 0; half < 2; half++) {
            const int ml = mt * 128 + wrow + mi * 16 + grp + 8 * half;
            if (ml >= Me) continue;
            const int pos = m0 + ml;
            #pragma unroll
            for (int nj = 0; nj < 8; nj++) {
                const int col = wcol + nj * 8 + 2 * tig;
                float v0 = acc[mi][nj][2 * half];
                float v1 = acc[mi][nj][2 * half + 1];
                if (IS_FF1) {
                    const float* bia = bias + (size_t)e * N + nt * 128;
                    float2 o;
                    o.x = __uint_as_float(f2tf32(gelu_exact(v0 + bia[col])));
                    o.y = __uint_as_float(f2tf32(gelu_exact(v1 + bia[col + 1])));
                    *(float2*)&g_hbuf[(size_t)pos * N + (size_t)nt * 128 + col] = o;
                } else {
                    float2 o; o.x = v0; o.y = v1;
                    *(float2*)&g_part[(size_t)kc * Tn * N + (size_t)pos * N + (size_t)nt * 128 + col] = o;
                }
            }
        }
    }
}

// ============================================================
// FF2 reduce: sum split-K partials + bias + residual, scatter to out
// ============================================================
__global__ __launch_bounds__(256) void ff2_reduce(
    const float* __restrict__ b2, float* __restrict__ out)
{
    const int idx = blockIdx.x * 256 + threadIdx.x;   // float4 index
    if (idx >= Tn * Dm / 4) return;
    const int pos = idx / (Dm / 4);
    const int c   = (idx % (Dm / 4)) * 4;
    const int tok = g_perm[pos];
    const int e   = g_top1[tok];

    float4 s = *(const float4*)&g_part[(size_t)pos * Dm + c];
    #pragma unroll
    for (int kc = 1; kc < KSP2; kc++) {
        float4 p = *(const float4*)&g_part[(size_t)kc * Tn * Dm + (size_t)pos * Dm + c];
        s.x += p.x; s.y += p.y; s.z += p.z; s.w += p.w;
    }
    float4 bb = *(const float4*)&b2[(size_t)e * Dm + c];
    float4 xr = *(const float4*)&g_x1[(size_t)tok * Dm + c];
    s.x += bb.x + xr.x; s.y += bb.y + xr.y; s.z += bb.z + xr.z; s.w += bb.w + xr.w;
    *(float4*)&out[(size_t)tok * Dm + c] = s;
}

// ============================================================
extern "C" void kernel_launch(void* const* d_in, const int* in_sizes, int n_in,
                              void* d_out, int out_size)
{
    const float* x    = (const float*)d_in[0];
    const float* ln1g = (const float*)d_in[1];
    const float* ln1b = (const float*)d_in[2];
    // d_in[3..6] = Wq,bq,Wk,bk — provably unused (attention collapses to v)
    const float* Wv   = (const float*)d_in[7];
    const float* bv   = (const float*)d_in[8];
    const float* ln2g = (const float*)d_in[9];
    const float* ln2b = (const float*)d_in[10];
    const float* Wg   = (const float*)d_in[11];
    const float* bg   = (const float*)d_in[12];
    const float* W1   = (const float*)d_in[13];
    const float* b1   = (const float*)d_in[14];
    const float* W2   = (const float*)d_in[15];
    const float* b2   = (const float*)d_in[16];
    float* out = (float*)d_out;

    // idempotent, host-side, not a stream op — safe under graph capture.
    cudaFuncSetAttribute(moe_gemm_cp<Dm, FFd, true, 1>,
                         cudaFuncAttributeMaxDynamicSharedMemorySize, GEMM_SMEM_BYTES);
    cudaFuncSetAttribute(moe_gemm_cp<FFd, Dm, false, KSP2>,
                         cudaFuncAttributeMaxDynamicSharedMemorySize, GEMM_SMEM_BYTES);

    prep_kernel<<<Tn / 4, 256>>>(x, ln1g, ln1b, Wv, bv, ln2g, ln2b, Wg, bg);
    bucket_kernel<<<1, 256>>>();
    moe_gemm_cp<Dm, FFd, true, 1>
        <<<dim3(FFd / 128, 13, NEx), 256, GEMM_SMEM_BYTES>>>(W1, b1);
    moe_gemm_cp<FFd, Dm, false, KSP2>
        <<<dim3(Dm / 128, 13, NEx * KSP2), 256, GEMM_SMEM_BYTES>>>(W2, nullptr);
    ff2_reduce<<<(Tn * Dm / 4 + 255) / 256, 256>>>(b2, out);
}

// round 11
// speedup vs baseline: 1.1183x; 1.1183x over previous
#include <cuda_runtime.h>
#include <cstdint>
#include <math.h>

#define Tn   1568
#define Dm   768
#define FFd  3072
#define NEx  8
#define HDh  64
#define KSP2 3          // split-K factor for FF2 (288 CTAs ~= one full wave)
#define STG  5          // cp.async pipeline stages (4 groups in flight)

// ---- scratch (allocation-free: __device__ globals) ----
__device__ float g_x1[Tn * Dm];            // residual after attention
__device__ float g_h2[Tn * Dm];            // LN2 output, tf32-rounded (MoE GEMM A)
__device__ float g_hbuf[Tn * FFd];         // FF1 activations, tf32-rounded, compact
__device__ float g_part[KSP2 * Tn * Dm];   // FF2 split-K partials
__device__ int   g_top1[Tn];
__device__ int   g_perm[Tn];
__device__ int   g_off[NEx + 1];

__device__ __forceinline__ unsigned f2tf32(float f) {
    unsigned r;
    asm("cvt.rna.tf32.f32 %0, %1;" : "=r"(r) : "f"(f));
    return r;
}

// ============================================================
// Kernel 1: LN1 + v-projection + residual + LN2 + gating
// Attention collapses algebraically: out_head(h) = v for all h.
// ============================================================
__global__ __launch_bounds__(256) void prep_kernel(
    const float* __restrict__ x,
    const float* __restrict__ ln1g, const float* __restrict__ ln1b,
    const float* __restrict__ Wv,   const float* __restrict__ bv,
    const float* __restrict__ ln2g, const float* __restrict__ ln2b,
    const float* __restrict__ Wg,   const float* __restrict__ bg)
{
    __shared__ float xs[4][Dm];
    __shared__ float hs[4][Dm];
    __shared__ float vs[4][HDh];
    __shared__ float red[16];

    const int tid  = threadIdx.x;
    const int base = blockIdx.x * 4;

    for (int t = 0; t < 4; t++) {
        const float* xr = x + (size_t)(base + t) * Dm;
        float s = 0.f, ss = 0.f, lv[3];
        #pragma unroll
        for (int i = 0; i < 3; i++) {
            int c = tid + i * 256;
            float v = xr[c];
            lv[i] = v; xs[t][c] = v; s += v; ss += v * v;
        }
        #pragma unroll
        for (int o = 16; o; o >>= 1) {
            s  += __shfl_xor_sync(0xffffffffu, s,  o);
            ss += __shfl_xor_sync(0xffffffffu, ss, o);
        }
        if ((tid & 31) == 0) { red[tid >> 5] = s; red[8 + (tid >> 5)] = ss; }
        __syncthreads();
        s = 0.f; ss = 0.f;
        #pragma unroll
        for (int i = 0; i < 8; i++) { s += red[i]; ss += red[8 + i]; }
        float mu   = s * (1.f / Dm);
        float var  = ss * (1.f / Dm) - mu * mu;
        float rstd = rsqrtf(var + 1e-5f);
        #pragma unroll
        for (int i = 0; i < 3; i++) {
            int c = tid + i * 256;
            hs[t][c] = (lv[i] - mu) * rstd * ln1g[c] + ln1b[c];
        }
        __syncthreads();
    }

    {   // v = LN1(x) @ Wv + bv
        const int t2 = tid >> 6, j = tid & 63;
        float a0 = 0.f, a1 = 0.f, a2 = 0.f, a3 = 0.f;
        for (int k = 0; k < Dm; k += 4) {
            a0 += hs[t2][k + 0] * Wv[(k + 0) * HDh + j];
            a1 += hs[t2][k + 1] * Wv[(k + 1) * HDh + j];
            a2 += hs[t2][k + 2] * Wv[(k + 2) * HDh + j];
            a3 += hs[t2][k + 3] * Wv[(k + 3) * HDh + j];
        }
        vs[t2][j] = (a0 + a1) + (a2 + a3) + bv[j];
    }
    __syncthreads();

    for (int t = 0; t < 4; t++) {   // residual + LN2
        const int tok = base + t;
        float s = 0.f, ss = 0.f, lv[3];
        #pragma unroll
        for (int i = 0; i < 3; i++) {
            int c = tid + i * 256;
            float v = xs[t][c] + vs[t][c & (HDh - 1)];
            lv[i] = v; s += v; ss += v * v;
            g_x1[(size_t)tok * Dm + c] = v;
        }
        #pragma unroll
        for (int o = 16; o; o >>= 1) {
            s  += __shfl_xor_sync(0xffffffffu, s,  o);
            ss += __shfl_xor_sync(0xffffffffu, ss, o);
        }
        if ((tid & 31) == 0) { red[tid >> 5] = s; red[8 + (tid >> 5)] = ss; }
        __syncthreads();
        s = 0.f; ss = 0.f;
        #pragma unroll
        for (int i = 0; i < 8; i++) { s += red[i]; ss += red[8 + i]; }
        float mu   = s * (1.f / Dm);
        float var  = ss * (1.f / Dm) - mu * mu;
        float rstd = rsqrtf(var + 1e-5f);
        #pragma unroll
        for (int i = 0; i < 3; i++) {
            int c = tid + i * 256;
            float h = (lv[i] - mu) * rstd * ln2g[c] + ln2b[c];
            hs[t][c] = h;                                  // fp32 for gating
            g_h2[(size_t)tok * Dm + c] = __uint_as_float(f2tf32(h));  // tf32-rna for GEMM A
        }
        __syncthreads();
    }

    // gate logits + argmax (fp32)
    const int wid = tid >> 5, lane = tid & 31;
    if (wid < 4) {
        float lg[8];
        #pragma unroll
        for (int e = 0; e < 8; e++) lg[e] = 0.f;
        for (int k = lane; k < Dm; k += 32) {
            float h = hs[wid][k];
            #pragma unroll
            for (int e = 0; e < 8; e++) lg[e] += h * Wg[k * 8 + e];
        }
        #pragma unroll
        for (int e = 0; e < 8; e++)
            #pragma unroll
            for (int o = 16; o; o >>= 1) lg[e] += __shfl_xor_sync(0xffffffffu, lg[e], o);
        if (lane == 0) {
            float best = lg[0] + bg[0]; int bi = 0;
            #pragma unroll
            for (int e = 1; e < 8; e++) {
                float v = lg[e] + bg[e];
                if (v > best) { best = v; bi = e; }
            }
            g_top1[base + wid] = bi;
        }
    }
}

// ============================================================
// Kernel 2: bucket tokens by expert (single block)
// ============================================================
__global__ void bucket_kernel()
{
    __shared__ int cnt[NEx];
    __shared__ int cur[NEx];
    const int tid = threadIdx.x;
    if (tid < NEx) cnt[tid] = 0;
    __syncthreads();
    for (int i = tid; i < Tn; i += 256) atomicAdd(&cnt[g_top1[i]], 1);
    __syncthreads();
    if (tid == 0) {
        int acc = 0;
        for (int e = 0; e < NEx; e++) { g_off[e] = acc; cur[e] = acc; acc += cnt[e]; }
        g_off[NEx] = acc;
    }
    __syncthreads();
    for (int i = tid; i < Tn; i += 256) {
        int e = g_top1[i];
        int p = atomicAdd(&cur[e], 1);
        g_perm[p] = i;
    }
}

__device__ __forceinline__ float gelu_exact(float v) { return v * normcdff(v); }

__device__ __forceinline__ void mma_tf32(float* c,
    unsigned a0, unsigned a1, unsigned a2, unsigned a3,
    unsigned b0, unsigned b1)
{
    asm volatile(
        "mma.sync.aligned.m16n8k8.row.col.f32.tf32.tf32.f32 "
        "{%0,%1,%2,%3}, {%4,%5,%6,%7}, {%8,%9}, {%0,%1,%2,%3};"
        : "+f"(c[0]), "+f"(c[1]), "+f"(c[2]), "+f"(c[3])
        : "r"(a0), "r"(a1), "r"(a2), "r"(a3), "r"(b0), "r"(b1));
}

__device__ __forceinline__ uint32_t smem_u32(const void* p) {
    return (uint32_t)__cvta_generic_to_shared(p);
}
__device__ __forceinline__ void cp16(uint32_t dst, const void* src) {
    asm volatile("cp.async.cg.shared.global [%0], [%1], 16;" :: "r"(dst), "l"(src));
}
__device__ __forceinline__ void cp16z(uint32_t dst, const void* src, int sz) {
    asm volatile("cp.async.cg.shared.global [%0], [%1], 16, %2;" :: "r"(dst), "l"(src), "r"(sz));
}

// ============================================================
// TF32 tensor-core MoE GEMM, cp.async 5-stage pipeline (4 groups in
// flight), BK=16, static stage indices via x5 unroll + static peel.
// Block tile 128x128, 8 warps of 32x64.
// A smem [128][20] (m-major, pad 20 -> conflict-free frag loads)
// B smem [16][136]  (k-major, pad 136 -> conflict-free frag loads)
// Weights fed as raw f32 (HW tf32 truncation); activations pre-rounded rna.
// ============================================================
#define LDAA 20
#define LDBB 136
#define GEMM_SMEM_BYTES ((STG * 128 * LDAA + STG * 16 * LDBB) * 4)

template<int K, int N, bool IS_FF1, int KSPLIT>
__global__ __launch_bounds__(256, 2) void moe_gemm_cp(
    const float* __restrict__ W, const float* __restrict__ bias)
{
    const int e  = blockIdx.z / KSPLIT;
    const int kc = blockIdx.z % KSPLIT;
    constexpr int KS = K / KSPLIT;
    constexpr int NITER = KS / 16;
    static_assert(NITER >= STG, "pipeline deeper than loop");

    const int m0 = g_off[e];
    const int Me = g_off[e + 1] - m0;
    const int mt = blockIdx.y;
    if (mt * 128 >= Me) return;
    const int nt = blockIdx.x;

    extern __shared__ float smem[];
    float (*As)[128][LDAA] = (float (*)[128][LDAA])smem;
    float (*Bs)[16][LDBB]  = (float (*)[16][LDBB])(smem + STG * 128 * LDAA);

    const int tid  = threadIdx.x;
    const int lane = tid & 31;
    const int w    = tid >> 5;
    const int grp  = lane >> 2, tig = lane & 3;
    const int wrow = (w & 3) * 32;
    const int wcol = (w >> 2) * 64;

    // ---- cp.async loader assignments ----
    const int ar0 = tid >> 2;            // A rows ar0, ar0+64
    const int akq = (tid & 3) * 4;       // A k-offset (floats)
    const int br0 = tid >> 5;            // B k-rows br0, br0+8
    const int bnq = (tid & 31) * 4;      // B n-offset (floats)

    const float* arowp[2]; int asz[2];
    #pragma unroll
    for (int i = 0; i < 2; i++) {
        int  mloc = mt * 128 + ar0 + i * 64;
        bool v    = mloc < Me;
        int  apos = m0 + (v ? mloc : 0);
        arowp[i] = (IS_FF1 ? &g_h2[(size_t)g_perm[apos] * K] : &g_hbuf[(size_t)apos * K])
                   + kc * KS + akq;
        asz[i] = v ? 16 : 0;
    }
    const float* __restrict__ Bbase =
        W + (size_t)e * K * N + (size_t)(kc * KS) * N + (size_t)nt * 128 + bnq;

    #define LOAD_STAGE(k0, st)                                                    \
        do {                                                                      \
            cp16z(smem_u32(&As[st][ar0][akq]),      arowp[0] + (k0), asz[0]);     \
            cp16z(smem_u32(&As[st][ar0 + 64][akq]), arowp[1] + (k0), asz[1]);     \
            cp16(smem_u32(&Bs[st][br0][bnq]),     Bbase + (size_t)((k0) + br0) * N);      \
            cp16(smem_u32(&Bs[st][br0 + 8][bnq]), Bbase + (size_t)((k0) + br0 + 8) * N);  \
            asm volatile("cp.async.commit_group;");                               \
        } while (0)

    float acc[2][8][4];
    #pragma unroll
    for (int i = 0; i < 2; i++)
        #pragma unroll
        for (int j = 0; j < 8; j++)
            #pragma unroll
            for (int r = 0; r < 4; r++) acc[i][j][r] = 0.f;

    // one BK=16 iteration with static stage index st
    #define ITER_BODY(st, kit)                                                        \
        do {                                                                          \
            if ((kit) + STG - 1 < NITER) {                                            \
                LOAD_STAGE(((kit) + STG - 1) * 16, ((st) + STG - 1) % STG);           \
            } else {                                                                  \
                asm volatile("cp.async.commit_group;");                               \
            }                                                                         \
            _Pragma("unroll")                                                         \
            for (int ks = 0; ks < 2; ks++) {                                          \
                const int kk = ks * 8;                                                \
                unsigned af[2][4];                                                    \
                _Pragma("unroll")                                                     \
                for (int mi = 0; mi < 2; mi++) {                                      \
                    const int mb = wrow + mi * 16;                                    \
                    af[mi][0] = __float_as_uint(As[st][mb + grp    ][kk + tig    ]);  \
                    af[mi][1] = __float_as_uint(As[st][mb + grp + 8][kk + tig    ]);  \
                    af[mi][2] = __float_as_uint(As[st][mb + grp    ][kk + tig + 4]);  \
                    af[mi][3] = __float_as_uint(As[st][mb + grp + 8][kk + tig + 4]);  \
                }                                                                     \
                _Pragma("unroll")                                                     \
                for (int nj = 0; nj < 8; nj++) {                                      \
                    const int nb = wcol + nj * 8;                                     \
                    unsigned b0 = __float_as_uint(Bs[st][kk + tig    ][nb + grp]);    \
                    unsigned b1 = __float_as_uint(Bs[st][kk + tig + 4][nb + grp]);    \
                    mma_tf32(acc[0][nj], af[0][0], af[0][1], af[0][2], af[0][3], b0, b1); \
                    mma_tf32(acc[1][nj], af[1][0], af[1][1], af[1][2], af[1][3], b0, b1); \
                }                                                                     \
            }                                                                         \
            asm volatile("cp.async.wait_group %0;" :: "n"(STG - 2));                  \
            __syncthreads();                                                          \
        } while (0)

    // prologue: stages 0..STG-2 in flight
    LOAD_STAGE(0,  0);
    LOAD_STAGE(16, 1);
    LOAD_STAGE(32, 2);
    LOAD_STAGE(48, 3);
    asm volatile("cp.async.wait_group %0;" :: "n"(STG - 2));
    __syncthreads();

    int it = 0;
    for (; it + STG <= NITER; it += STG) {
        ITER_BODY(0, it + 0);
        ITER_BODY(1, it + 1);
        ITER_BODY(2, it + 2);
        ITER_BODY(3, it + 3);
        ITER_BODY(4, it + 4);
    }
    // statically-peeled remainder (main loop exits with it % STG == 0,
    // so consumed stage indices restart at 0; NITER % STG is constexpr)
    if (NITER % STG > 0) ITER_BODY(0, (NITER / STG) * STG + 0);
    if (NITER % STG > 1) ITER_BODY(1, (NITER / STG) * STG + 1);
    if (NITER % STG > 2) ITER_BODY(2, (NITER / STG) * STG + 2);
    if (NITER % STG > 3) ITER_BODY(3, (NITER / STG) * STG + 3);

    #undef ITER_BODY
    #undef LOAD_STAGE

    // ---- epilogue ----
    // element (mi, nj, reg): row = wrow + mi*16 + grp + 8*(reg>>1)
    //                        col = wcol + nj*8 + 2*tig + (reg&1)
    #pragma unroll
    for (int mi = 0; mi < 2; mi++) {
        #pragma unroll
        for (int half = 0; half < 2; half++) {
            const int ml = mt * 128 + wrow + mi * 16 + grp + 8 * half;
            if (ml >= Me) continue;
            const int pos = m0 + ml;
            #pragma unroll
            for (int nj = 0; nj < 8; nj++) {
                const int col = wcol + nj * 8 + 2 * tig;
                float v0 = acc[mi][nj][2 * half];
                float v1 = acc[mi][nj][2 * half + 1];
                if (IS_FF1) {
                    const float* bia = bias + (size_t)e * N + nt * 128;
                    float2 o;
                    o.x = __uint_as_float(f2tf32(gelu_exact(v0 + bia[col])));
                    o.y = __uint_as_float(f2tf32(gelu_exact(v1 + bia[col + 1])));
                    *(float2*)&g_hbuf[(size_t)pos * N + (size_t)nt * 128 + col] = o;
                } else {
                    float2 o; o.x = v0; o.y = v1;
                    *(float2*)&g_part[(size_t)kc * Tn * N + (size_t)pos * N + (size_t)nt * 128 + col] = o;
                }
            }
        }
    }
}

// ============================================================
// FF2 reduce: sum split-K partials + bias + residual, scatter to out
// ============================================================
__global__ __launch_bounds__(256) void ff2_reduce(
    const float* __restrict__ b2, float* __restrict__ out)
{
    const int idx = blockIdx.x * 256 + threadIdx.x;   // float4 index
    if (idx >= Tn * Dm / 4) return;
    const int pos = idx / (Dm / 4);
    const int c   = (idx % (Dm / 4)) * 4;
    const int tok = g_perm[pos];
    const int e   = g_top1[tok];

    float4 s = *(const float4*)&g_part[(size_t)pos * Dm + c];
    #pragma unroll
    for (int kc = 1; kc < KSP2; kc++) {
        float4 p = *(const float4*)&g_part[(size_t)kc * Tn * Dm + (size_t)pos * Dm + c];
        s.x += p.x; s.y += p.y; s.z += p.z; s.w += p.w;
    }
    float4 bb = *(const float4*)&b2[(size_t)e * Dm + c];
    float4 xr = *(const float4*)&g_x1[(size_t)tok * Dm + c];
    s.x += bb.x + xr.x; s.y += bb.y + xr.y; s.z += bb.z + xr.z; s.w += bb.w + xr.w;
    *(float4*)&out[(size_t)tok * Dm + c] = s;
}

// ============================================================
extern "C" void kernel_launch(void* const* d_in, const int* in_sizes, int n_in,
                              void* d_out, int out_size)
{
    const float* x    = (const float*)d_in[0];
    const float* ln1g = (const float*)d_in[1];
    const float* ln1b = (const float*)d_in[2];
    // d_in[3..6] = Wq,bq,Wk,bk — provably unused (attention collapses to v)
    const float* Wv   = (const float*)d_in[7];
    const float* bv   = (const float*)d_in[8];
    const float* ln2g = (const float*)d_in[9];
    const float* ln2b = (const float*)d_in[10];
    const float* Wg   = (const float*)d_in[11];
    const float* bg   = (const float*)d_in[12];
    const float* W1   = (const float*)d_in[13];
    const float* b1   = (const float*)d_in[14];
    const float* W2   = (const float*)d_in[15];
    const float* b2   = (const float*)d_in[16];
    float* out = (float*)d_out;

    // idempotent, host-side, not a stream op — safe under graph capture.
    cudaFuncSetAttribute(moe_gemm_cp<Dm, FFd, true, 1>,
                         cudaFuncAttributeMaxDynamicSharedMemorySize, GEMM_SMEM_BYTES);
    cudaFuncSetAttribute(moe_gemm_cp<FFd, Dm, false, KSP2>,
                         cudaFuncAttributeMaxDynamicSharedMemorySize, GEMM_SMEM_BYTES);

    prep_kernel<<<Tn / 4, 256>>>(x, ln1g, ln1b, Wv, bv, ln2g, ln2b, Wg, bg);
    bucket_kernel<<<1, 256>>>();
    moe_gemm_cp<Dm, FFd, true, 1>
        <<<dim3(FFd / 128, 13, NEx), 256, GEMM_SMEM_BYTES>>>(W1, b1);
    moe_gemm_cp<FFd, Dm, false, KSP2>
        <<<dim3(Dm / 128, 13, NEx * KSP2), 256, GEMM_SMEM_BYTES>>>(W2, nullptr);
    ff2_reduce<<<(Tn * Dm / 4 + 255) / 256, 256>>>(b2, out);
}